// round 4
// baseline (speedup 1.0000x reference)
#include <cuda_runtime.h>
#include <math.h>

#define Bb 16
#define Nn 1000
#define Hh 128
#define Mm 2
#define Tt 16
#define Ss 8          // chunks per (b,m) in glimpse pass
#define CN 125        // Nn / Ss
#define NEGC 1e8f
#define CCLIP 10.0f

// ---------------- scratch (static device globals; no allocation) ----------------
#define BNH (Bb*Nn*Hh)
__device__ __align__(16) float d_r1[Mm*BNH];
__device__ __align__(16) float d_v1[Mm*BNH];
__device__ __align__(16) float d_r3[Mm*BNH];
__device__ __align__(16) float d_v3[Mm*BNH];
__device__ __align__(16) float d_r4[Mm*BNH];
__device__ __align__(16) float d_v4[Mm*BNH];
__device__ __align__(16) float d_r2[BNH];
__device__ __align__(16) float d_hmean[Bb*Hh];
__device__ __align__(16) float d_q0[Bb*2*Hh];    // concat(h_mean, prev)
__device__ __align__(16) float d_qb[Bb*Hh];      // current query
__device__ __align__(16) float d_mask[Bb*Nn];
__device__ __align__(16) float d_pmax[Bb*Mm*Ss];
__device__ __align__(16) float d_pZ[Bb*Mm*Ss];
__device__ __align__(16) float d_pacc[Bb*Mm*Ss*Hh];

__device__ __forceinline__ float fast_tanh(float x) {
    float y;
    asm("tanh.approx.f32 %0, %1;" : "=f"(y) : "f"(x));
    return y;
}

// ---------------- precompute GEMM: 13 slabs of [16000x128] @ [128x128] ----------------
struct GemmW {
    const float* Wref1; const float* Vec1;
    const float* Wref3; const float* Vec3;
    const float* Wref4; const float* Vec4;
    const float* Wref2;
};

__global__ __launch_bounds__(256) void gemm_kernel(const float* __restrict__ A, GemmW gw) {
    __shared__ float As[8][132];
    __shared__ float Bs[8][132];

    int s = blockIdx.y;
    int m = s & 1;
    const float* W; float* D;
    switch (s >> 1) {
        case 0: W = gw.Wref1; D = d_r1; break;
        case 1: W = gw.Vec1;  D = d_v1; break;
        case 2: W = gw.Wref3; D = d_r3; break;
        case 3: W = gw.Vec3;  D = d_v3; break;
        case 4: W = gw.Wref4; D = d_r4; break;
        case 5: W = gw.Vec4;  D = d_v4; break;
        default: W = gw.Wref2; D = d_r2; break;   // s==12 -> m==0
    }
    W += (size_t)m * Hh * Hh;
    D += (size_t)m * BNH;

    int tid = threadIdx.x;
    int tx = tid & 15, ty = tid >> 4;
    int rowBase = blockIdx.x * 128;

    int arow = tid >> 1, akq = (tid & 1) * 4;
    int brow = tid >> 5, bcol = (tid & 31) * 4;

    float acc[8][8];
#pragma unroll
    for (int i = 0; i < 8; i++)
#pragma unroll
        for (int j = 0; j < 8; j++) acc[i][j] = 0.f;

    for (int k0 = 0; k0 < 128; k0 += 8) {
        float4 av = *(const float4*)&A[(size_t)(rowBase + arow) * 128 + k0 + akq];
        As[akq + 0][arow] = av.x;
        As[akq + 1][arow] = av.y;
        As[akq + 2][arow] = av.z;
        As[akq + 3][arow] = av.w;
        float4 bv = *(const float4*)&W[(size_t)(k0 + brow) * 128 + bcol];
        *(float4*)&Bs[brow][bcol] = bv;
        __syncthreads();
#pragma unroll
        for (int kk = 0; kk < 8; kk++) {
            float4 a0 = *(float4*)&As[kk][ty * 8];
            float4 a1 = *(float4*)&As[kk][ty * 8 + 4];
            float4 b0 = *(float4*)&Bs[kk][tx * 4];
            float4 b1 = *(float4*)&Bs[kk][64 + tx * 4];
            float a[8] = {a0.x, a0.y, a0.z, a0.w, a1.x, a1.y, a1.z, a1.w};
            float b[8] = {b0.x, b0.y, b0.z, b0.w, b1.x, b1.y, b1.z, b1.w};
#pragma unroll
            for (int i = 0; i < 8; i++)
#pragma unroll
                for (int j = 0; j < 8; j++) acc[i][j] = fmaf(a[i], b[j], acc[i][j]);
        }
        __syncthreads();
    }

    int r0 = rowBase + ty * 8;
#pragma unroll
    for (int i = 0; i < 8; i++) {
        float4 o0 = make_float4(acc[i][0], acc[i][1], acc[i][2], acc[i][3]);
        float4 o1 = make_float4(acc[i][4], acc[i][5], acc[i][6], acc[i][7]);
        *(float4*)&D[(size_t)(r0 + i) * Hh + tx * 4] = o0;
        *(float4*)&D[(size_t)(r0 + i) * Hh + 64 + tx * 4] = o1;
    }
}

// ---------------- h_mean ----------------
__global__ __launch_bounds__(256) void hmean_kernel(const float* __restrict__ enc) {
    int b = blockIdx.x;
    int h = threadIdx.x & 127;
    int part = threadIdx.x >> 7;
    float sum = 0.f;
    int n0 = part * 500;
    for (int n = n0; n < n0 + 500; n++) sum += enc[(size_t)(b * Nn + n) * Hh + h];
    __shared__ float sp[256];
    sp[threadIdx.x] = sum;
    __syncthreads();
    if (part == 0) d_hmean[b * Hh + h] = (sp[h] + sp[128 + h]) * (1.0f / (float)Nn);
}

// ---------------- init: mask, q0 = concat(h_mean, dec_inp) ----------------
__global__ __launch_bounds__(256) void init_kernel(const float* __restrict__ mask0,
                                                   const float* __restrict__ dec_inp) {
    int b = blockIdx.x, tid = threadIdx.x;
    if (tid < 128) {
        d_q0[b * 256 + tid] = d_hmean[b * Hh + tid];
        d_q0[b * 256 + 128 + tid] = dec_inp[tid];
    }
    for (int n = tid; n < Nn; n += 256) d_mask[b * Nn + n] = mask0[b * Nn + n];
}

// ---------------- glimpse pass 1: chunked online-softmax over N ----------------
// grid (Ss, Mm, Bb), 256 threads.
// which: 0 -> (r1,v1, qsrc=d_q0, Din=256), 1 -> (r3,v3, d_qb, 128), 2 -> (r4,v4, d_qb, 128)
__global__ __launch_bounds__(256) void glimpse_chunk(int which, int Din,
                                                     const float* __restrict__ Wq) {
    const float* rT   = (which == 0) ? d_r1 : (which == 1) ? d_r3 : d_r4;
    const float* vT   = (which == 0) ? d_v1 : (which == 1) ? d_v3 : d_v4;
    const float* qsrc = (which == 0) ? d_q0 : d_qb;

    int c = blockIdx.x, m = blockIdx.y, b = blockIdx.z;
    int tid = threadIdx.x, lane = tid & 31, w = tid >> 5;

    __shared__ __align__(16) float sq0[256];
    __shared__ float sproj[256];
    __shared__ __align__(16) float sq[128];
    __shared__ float wmax[8], wZ[8];
    __shared__ __align__(16) float wacc[8 * 128];

    if (tid < Din) sq0[tid] = qsrc[b * Din + tid];
    __syncthreads();

    // per-head query projection q[h] = sum_i q0[i] * Wq[m, i, h]
    {
        int h = tid & 127, part = tid >> 7;
        const float* Wqm = Wq + (size_t)m * Din * Hh;
        int half = Din >> 1;
        int i0 = part * half;
        float acc = 0.f;
        for (int i = i0; i < i0 + half; i++) acc = fmaf(sq0[i], Wqm[(size_t)i * Hh + h], acc);
        sproj[tid] = acc;
        __syncthreads();
        if (part == 0) sq[h] = sproj[h] + sproj[128 + h];
        __syncthreads();
    }

    float4 q4 = *(float4*)&sq[lane * 4];
    const float* rBase = rT + (size_t)(m * Bb + b) * Nn * Hh;
    const float* vBase = vT + (size_t)(m * Bb + b) * Nn * Hh;
    const float* maskb = d_mask + b * Nn;

    float rmax = -1e30f, rZ = 0.f;
    float4 racc = make_float4(0.f, 0.f, 0.f, 0.f);

    int n0 = c * CN;
    for (int n = n0 + w; n < n0 + CN; n += 8) {
        float4 r4 = *(const float4*)&rBase[(size_t)n * Hh + lane * 4];
        float4 v4 = *(const float4*)&vBase[(size_t)n * Hh + lane * 4];
        float dot = fast_tanh(q4.x + r4.x) * v4.x;
        dot = fmaf(fast_tanh(q4.y + r4.y), v4.y, dot);
        dot = fmaf(fast_tanh(q4.z + r4.z), v4.z, dot);
        dot = fmaf(fast_tanh(q4.w + r4.w), v4.w, dot);
#pragma unroll
        for (int off = 16; off; off >>= 1) dot += __shfl_xor_sync(0xffffffffu, dot, off);
        float sN = CCLIP * tanhf(dot) - NEGC * maskb[n];
        if (sN <= rmax) {
            float p = __expf(sN - rmax);
            rZ += p;
            racc.x = fmaf(p, r4.x, racc.x);
            racc.y = fmaf(p, r4.y, racc.y);
            racc.z = fmaf(p, r4.z, racc.z);
            racc.w = fmaf(p, r4.w, racc.w);
        } else {
            float sc = __expf(rmax - sN);
            rZ = fmaf(rZ, sc, 1.f);
            racc.x = fmaf(racc.x, sc, r4.x);
            racc.y = fmaf(racc.y, sc, r4.y);
            racc.z = fmaf(racc.z, sc, r4.z);
            racc.w = fmaf(racc.w, sc, r4.w);
            rmax = sN;
        }
    }

    if (lane == 0) { wmax[w] = rmax; wZ[w] = rZ; }
    *(float4*)&wacc[w * 128 + lane * 4] = racc;
    __syncthreads();

    if (tid < 128) {
        float cm = wmax[0];
#pragma unroll
        for (int j = 1; j < 8; j++) cm = fmaxf(cm, wmax[j]);
        float z = 0.f, g = 0.f;
#pragma unroll
        for (int j = 0; j < 8; j++) {
            float e = __expf(wmax[j] - cm);
            z = fmaf(wZ[j], e, z);
            g = fmaf(wacc[j * 128 + tid], e, g);
        }
        int pidx = (b * Mm + m) * Ss + c;
        d_pacc[pidx * Hh + tid] = g;
        if (tid == 0) { d_pmax[pidx] = cm; d_pZ[pidx] = z; }
    }
}

// ---------------- glimpse pass 2: combine chunks, merge heads -> qb ----------------
__global__ __launch_bounds__(256) void glimpse_combine(const float* __restrict__ Wmh) {
    int b = blockIdx.x, tid = threadIdx.x;   // tid = m*128 + h
    __shared__ float sg[256];
    int base = (b * Mm + (tid >> 7)) * Ss;
    int h = tid & 127;
    float cm = d_pmax[base];
#pragma unroll
    for (int c = 1; c < Ss; c++) cm = fmaxf(cm, d_pmax[base + c]);
    float z = 0.f, g = 0.f;
#pragma unroll
    for (int c = 0; c < Ss; c++) {
        float e = __expf(d_pmax[base + c] - cm);
        z = fmaf(d_pZ[base + c], e, z);
        g = fmaf(d_pacc[(base + c) * Hh + h], e, g);
    }
    sg[tid] = g / z;
    __syncthreads();
    if (tid < 128) {
        float o = 0.f;
#pragma unroll 4
        for (int j = 0; j < 256; j++) o = fmaf(sg[j], Wmh[(size_t)j * Hh + tid], o);
        d_qb[b * Hh + tid] = o;
    }
}

// ---------------- pointer: logits, log_softmax, argmax, state update ----------------
__global__ __launch_bounds__(256) void pointer_kernel(const float* __restrict__ enc,
                                                      const float* __restrict__ Wq2,
                                                      const float* __restrict__ Vec2,
                                                      float* __restrict__ out, int t) {
    int b = blockIdx.x, tid = threadIdx.x, lane = tid & 31, w = tid >> 5;
    __shared__ float sq0[128];
    __shared__ float sproj[256];
    __shared__ __align__(16) float sq[128];
    __shared__ float su[1000];
    __shared__ float rv[256];
    __shared__ int ri[256];

    if (tid < 128) sq0[tid] = d_qb[b * Hh + tid];
    __syncthreads();
    {
        int h = tid & 127, part = tid >> 7;
        int i0 = part * 64;
        float acc = 0.f;
        for (int i = i0; i < i0 + 64; i++) acc = fmaf(sq0[i], Wq2[(size_t)i * Hh + h], acc);
        sproj[tid] = acc;
        __syncthreads();
        if (part == 0) sq[h] = sproj[h] + sproj[128 + h];
        __syncthreads();
    }

    float4 q4 = *(float4*)&sq[lane * 4];
    float4 v2 = *(const float4*)&Vec2[lane * 4];
    for (int n = w; n < Nn; n += 8) {
        float4 r4 = *(const float4*)&d_r2[(size_t)(b * Nn + n) * Hh + lane * 4];
        float dot = fast_tanh(q4.x + r4.x) * v2.x;
        dot = fmaf(fast_tanh(q4.y + r4.y), v2.y, dot);
        dot = fmaf(fast_tanh(q4.z + r4.z), v2.z, dot);
        dot = fmaf(fast_tanh(q4.w + r4.w), v2.w, dot);
#pragma unroll
        for (int off = 16; off; off >>= 1) dot += __shfl_xor_sync(0xffffffffu, dot, off);
        if (lane == 0) su[n] = CCLIP * tanhf(dot) - NEGC * d_mask[b * Nn + n];
    }
    __syncthreads();

    // argmax (first index wins on ties, matching jnp.argmax)
    float best = -1e30f; int bidx = 0;
    for (int n = tid; n < Nn; n += 256) {
        float vv = su[n];
        if (vv > best) { best = vv; bidx = n; }
    }
    rv[tid] = best; ri[tid] = bidx;
    __syncthreads();
    for (int sstep = 128; sstep; sstep >>= 1) {
        if (tid < sstep) {
            float v2r = rv[tid + sstep]; int i2 = ri[tid + sstep];
            if (v2r > rv[tid] || (v2r == rv[tid] && i2 < ri[tid])) { rv[tid] = v2r; ri[tid] = i2; }
        }
        __syncthreads();
    }
    float umax = rv[0]; int sel = ri[0];

    float z = 0.f;
    for (int n = tid; n < Nn; n += 256) z += __expf(su[n] - umax);
    sproj[tid] = z;
    __syncthreads();
    for (int sstep = 128; sstep; sstep >>= 1) {
        if (tid < sstep) sproj[tid] += sproj[tid + sstep];
        __syncthreads();
    }
    float lse = umax + logf(sproj[0]);

    for (int n = tid; n < Nn; n += 256)
        out[((size_t)t * Bb + b) * Nn + n] = su[n] - lse;

    if (tid == 0) {
        out[(size_t)Tt * Bb * Nn + t * Bb + b] = (float)sel;
        d_mask[b * Nn + sel] = 1.0f;
    }
    if (tid < 128)
        d_q0[b * 256 + 128 + tid] = enc[((size_t)b * Nn + sel) * Hh + tid];
}

// ---------------- host launcher ----------------
extern "C" void kernel_launch(void* const* d_in, const int* in_sizes, int n_in,
                              void* d_out, int out_size) {
    const float* enc    = (const float*)d_in[0];
    const float* mask0  = (const float*)d_in[1];
    const float* Wq1    = (const float*)d_in[2];
    const float* Wref1  = (const float*)d_in[3];
    const float* Vec1   = (const float*)d_in[4];
    const float* Wq3    = (const float*)d_in[5];
    const float* Wref3  = (const float*)d_in[6];
    const float* Vec3   = (const float*)d_in[7];
    const float* Wq4    = (const float*)d_in[8];
    const float* Wref4  = (const float*)d_in[9];
    const float* Vec4   = (const float*)d_in[10];
    const float* Wmh    = (const float*)d_in[11];
    const float* Wq2    = (const float*)d_in[12];
    const float* Wref2  = (const float*)d_in[13];
    const float* Vec2   = (const float*)d_in[14];
    const float* dec_inp = (const float*)d_in[15];
    float* out = (float*)d_out;

    GemmW gw{Wref1, Vec1, Wref3, Vec3, Wref4, Vec4, Wref2};
    gemm_kernel<<<dim3(125, 13), 256>>>(enc, gw);
    hmean_kernel<<<Bb, 256>>>(enc);
    init_kernel<<<Bb, 256>>>(mask0, dec_inp);

    for (int t = 0; t < Tt; t++) {
        glimpse_chunk<<<dim3(Ss, Mm, Bb), 256>>>(0, 256, Wq1);
        glimpse_combine<<<Bb, 256>>>(Wmh);
        glimpse_chunk<<<dim3(Ss, Mm, Bb), 256>>>(1, 128, Wq3);
        glimpse_combine<<<Bb, 256>>>(Wmh);
        glimpse_chunk<<<dim3(Ss, Mm, Bb), 256>>>(2, 128, Wq4);
        glimpse_combine<<<Bb, 256>>>(Wmh);
        pointer_kernel<<<Bb, 256>>>(enc, Wq2, Vec2, out, t);
    }
    (void)in_sizes; (void)n_in; (void)out_size;
}

// round 5
// speedup vs baseline: 2.2509x; 2.2509x over previous
#include <cuda_runtime.h>
#include <math.h>

#define Bb 16
#define Nn 1000
#define Hh 128
#define Mm 2
#define Tt 16
#define Ss 25         // chunks per (b,m) in glimpse pass
#define CN 40         // Nn / Ss
#define NEGC 1e8f
#define CCLIP 10.0f

// ---------------- scratch (static device globals; no allocation) ----------------
#define BNH (Bb*Nn*Hh)
__device__ __align__(16) float d_r1[Mm*BNH];
__device__ __align__(16) float d_v1[Mm*BNH];
__device__ __align__(16) float d_r3[Mm*BNH];
__device__ __align__(16) float d_v3[Mm*BNH];
__device__ __align__(16) float d_r4[Mm*BNH];
__device__ __align__(16) float d_v4[Mm*BNH];
__device__ __align__(16) float d_r2[BNH];
__device__ __align__(16) float d_hmean[Bb*Hh];
__device__ __align__(16) float d_q0[Bb*2*Hh];    // concat(h_mean, prev)
__device__ __align__(16) float d_qb[Bb*Hh];      // current query
__device__ __align__(16) float d_mask[Bb*Nn];
__device__ __align__(16) float d_pZ[Bb*Mm*Ss];
__device__ __align__(16) float d_pacc[Bb*Mm*Ss*Hh];

__device__ __forceinline__ float fast_tanh(float x) {
    float y;
    asm("tanh.approx.f32 %0, %1;" : "=f"(y) : "f"(x));
    return y;
}

// ---------------- precompute GEMM: 13 slabs of [16000x128] @ [128x128] ----------------
struct GemmW {
    const float* Wref1; const float* Vec1;
    const float* Wref3; const float* Vec3;
    const float* Wref4; const float* Vec4;
    const float* Wref2;
};

__global__ __launch_bounds__(256) void gemm_kernel(const float* __restrict__ A, GemmW gw) {
    __shared__ float As[8][132];
    __shared__ float Bs[8][132];

    int s = blockIdx.y;
    int m = s & 1;
    const float* W; float* D;
    switch (s >> 1) {
        case 0: W = gw.Wref1; D = d_r1; break;
        case 1: W = gw.Vec1;  D = d_v1; break;
        case 2: W = gw.Wref3; D = d_r3; break;
        case 3: W = gw.Vec3;  D = d_v3; break;
        case 4: W = gw.Wref4; D = d_r4; break;
        case 5: W = gw.Vec4;  D = d_v4; break;
        default: W = gw.Wref2; D = d_r2; break;   // s==12 -> m==0
    }
    W += (size_t)m * Hh * Hh;
    D += (size_t)m * BNH;

    int tid = threadIdx.x;
    int tx = tid & 15, ty = tid >> 4;
    int rowBase = blockIdx.x * 128;

    int arow = tid >> 1, akq = (tid & 1) * 4;
    int brow = tid >> 5, bcol = (tid & 31) * 4;

    float acc[8][8];
#pragma unroll
    for (int i = 0; i < 8; i++)
#pragma unroll
        for (int j = 0; j < 8; j++) acc[i][j] = 0.f;

    for (int k0 = 0; k0 < 128; k0 += 8) {
        float4 av = *(const float4*)&A[(size_t)(rowBase + arow) * 128 + k0 + akq];
        As[akq + 0][arow] = av.x;
        As[akq + 1][arow] = av.y;
        As[akq + 2][arow] = av.z;
        As[akq + 3][arow] = av.w;
        float4 bv = *(const float4*)&W[(size_t)(k0 + brow) * 128 + bcol];
        *(float4*)&Bs[brow][bcol] = bv;
        __syncthreads();
#pragma unroll
        for (int kk = 0; kk < 8; kk++) {
            float4 a0 = *(float4*)&As[kk][ty * 8];
            float4 a1 = *(float4*)&As[kk][ty * 8 + 4];
            float4 b0 = *(float4*)&Bs[kk][tx * 4];
            float4 b1 = *(float4*)&Bs[kk][64 + tx * 4];
            float a[8] = {a0.x, a0.y, a0.z, a0.w, a1.x, a1.y, a1.z, a1.w};
            float b[8] = {b0.x, b0.y, b0.z, b0.w, b1.x, b1.y, b1.z, b1.w};
#pragma unroll
            for (int i = 0; i < 8; i++)
#pragma unroll
                for (int j = 0; j < 8; j++) acc[i][j] = fmaf(a[i], b[j], acc[i][j]);
        }
        __syncthreads();
    }

    int r0 = rowBase + ty * 8;
#pragma unroll
    for (int i = 0; i < 8; i++) {
        float4 o0 = make_float4(acc[i][0], acc[i][1], acc[i][2], acc[i][3]);
        float4 o1 = make_float4(acc[i][4], acc[i][5], acc[i][6], acc[i][7]);
        *(float4*)&D[(size_t)(r0 + i) * Hh + tx * 4] = o0;
        *(float4*)&D[(size_t)(r0 + i) * Hh + 64 + tx * 4] = o1;
    }
}

// ---------------- h_mean ----------------
__global__ __launch_bounds__(256) void hmean_kernel(const float* __restrict__ enc) {
    int b = blockIdx.x;
    int h = threadIdx.x & 127;
    int part = threadIdx.x >> 7;
    float sum = 0.f;
    int n0 = part * 500;
    for (int n = n0; n < n0 + 500; n++) sum += enc[(size_t)(b * Nn + n) * Hh + h];
    __shared__ float sp[256];
    sp[threadIdx.x] = sum;
    __syncthreads();
    if (part == 0) d_hmean[b * Hh + h] = (sp[h] + sp[128 + h]) * (1.0f / (float)Nn);
}

// ---------------- init: mask, q0 = concat(h_mean, dec_inp) ----------------
__global__ __launch_bounds__(256) void init_kernel(const float* __restrict__ mask0,
                                                   const float* __restrict__ dec_inp) {
    int b = blockIdx.x, tid = threadIdx.x;
    if (tid < 128) {
        d_q0[b * 256 + tid] = d_hmean[b * Hh + tid];
        d_q0[b * 256 + 128 + tid] = dec_inp[tid];
    }
    for (int n = tid; n < Nn; n += 256) d_mask[b * Nn + n] = mask0[b * Nn + n];
}

// ---------------- glimpse pass 1: fixed-shift softmax partials over N chunks --------
// Scores are bounded above by CCLIP (=10): s = 10*tanh(.) - 1e8*mask. So exp(s-10)
// is a valid stable softmax numerator (masked rows underflow to exactly 0).
// grid (Ss, Mm, Bb), 256 threads.
// which: 0 -> (r1,v1, qsrc=d_q0, Din=256), 1 -> (r3,v3, d_qb, 128), 2 -> (r4,v4, d_qb, 128)
__global__ __launch_bounds__(256) void glimpse_chunk(int which, int Din,
                                                     const float* __restrict__ Wq) {
    const float* rT   = (which == 0) ? d_r1 : (which == 1) ? d_r3 : d_r4;
    const float* vT   = (which == 0) ? d_v1 : (which == 1) ? d_v3 : d_v4;
    const float* qsrc = (which == 0) ? d_q0 : d_qb;

    int c = blockIdx.x, m = blockIdx.y, b = blockIdx.z;
    int tid = threadIdx.x, lane = tid & 31, w = tid >> 5;

    __shared__ __align__(16) float sq0[256];
    __shared__ float sproj[256];
    __shared__ __align__(16) float sq[128];
    __shared__ float wZ[8];
    __shared__ __align__(16) float wacc[8 * 128];

    if (tid < Din) sq0[tid] = qsrc[b * Din + tid];
    __syncthreads();

    // per-head query projection q[h] = sum_i q0[i] * Wq[m, i, h]
    {
        int h = tid & 127, part = tid >> 7;
        const float* Wqm = Wq + (size_t)m * Din * Hh;
        int half = Din >> 1;
        int i0 = part * half;
        float acc = 0.f;
#pragma unroll 8
        for (int i = i0; i < i0 + half; i++) acc = fmaf(sq0[i], Wqm[(size_t)i * Hh + h], acc);
        sproj[tid] = acc;
        __syncthreads();
        if (part == 0) sq[h] = sproj[h] + sproj[128 + h];
        __syncthreads();
    }

    float4 q4 = *(float4*)&sq[lane * 4];
    const float* rBase = rT + (size_t)(m * Bb + b) * Nn * Hh;
    const float* vBase = vT + (size_t)(m * Bb + b) * Nn * Hh;
    const float* maskb = d_mask + b * Nn;

    float Z = 0.f;
    float4 racc = make_float4(0.f, 0.f, 0.f, 0.f);

    int n0 = c * CN;
#pragma unroll
    for (int i = 0; i < CN / 8; i++) {
        int n = n0 + w + i * 8;
        float4 r4 = *(const float4*)&rBase[(size_t)n * Hh + lane * 4];
        float4 v4 = *(const float4*)&vBase[(size_t)n * Hh + lane * 4];
        float dot = fast_tanh(q4.x + r4.x) * v4.x;
        dot = fmaf(fast_tanh(q4.y + r4.y), v4.y, dot);
        dot = fmaf(fast_tanh(q4.z + r4.z), v4.z, dot);
        dot = fmaf(fast_tanh(q4.w + r4.w), v4.w, dot);
#pragma unroll
        for (int off = 16; off; off >>= 1) dot += __shfl_xor_sync(0xffffffffu, dot, off);
        float s = CCLIP * fast_tanh(dot) - NEGC * maskb[n];
        float p = __expf(s - CCLIP);        // <= 1; masked -> exactly 0
        Z += p;
        racc.x = fmaf(p, r4.x, racc.x);
        racc.y = fmaf(p, r4.y, racc.y);
        racc.z = fmaf(p, r4.z, racc.z);
        racc.w = fmaf(p, r4.w, racc.w);
    }

    if (lane == 0) wZ[w] = Z;
    *(float4*)&wacc[w * 128 + lane * 4] = racc;
    __syncthreads();

    if (tid < 128) {
        float z = 0.f, g = 0.f;
#pragma unroll
        for (int j = 0; j < 8; j++) {
            z += wZ[j];
            g += wacc[j * 128 + tid];
        }
        int pidx = (b * Mm + m) * Ss + c;
        d_pacc[pidx * Hh + tid] = g;
        if (tid == 0) d_pZ[pidx] = z;
    }
}

// ---------------- glimpse pass 2: combine chunks, merge heads -> qb ----------------
__global__ __launch_bounds__(256) void glimpse_combine(const float* __restrict__ Wmh) {
    int b = blockIdx.x, tid = threadIdx.x;   // tid = m*128 + h
    __shared__ float sg[256];
    __shared__ float sp2[256];
    int base = (b * Mm + (tid >> 7)) * Ss;
    int h = tid & 127;
    float z = 0.f, g = 0.f;
#pragma unroll
    for (int c = 0; c < Ss; c++) {
        z += d_pZ[base + c];
        g += d_pacc[(base + c) * Hh + h];
    }
    sg[tid] = g / z;
    __syncthreads();
    // qb[h] = sum_j sg[j] * Wmh[j,h], split j-range over 2 halves
    {
        int hh = tid & 127, part = tid >> 7;
        int j0 = part * 128;
        float o = 0.f;
#pragma unroll 8
        for (int j = j0; j < j0 + 128; j++) o = fmaf(sg[j], Wmh[(size_t)j * Hh + hh], o);
        sp2[tid] = o;
        __syncthreads();
        if (part == 0) d_qb[b * Hh + hh] = sp2[hh] + sp2[128 + hh];
    }
}

// ---------------- pointer: logits, log_softmax, argmax, state update ----------------
__global__ __launch_bounds__(1024) void pointer_kernel(const float* __restrict__ enc,
                                                       const float* __restrict__ Wq2,
                                                       const float* __restrict__ Vec2,
                                                       float* __restrict__ out, int t) {
    int b = blockIdx.x, tid = threadIdx.x, lane = tid & 31, w = tid >> 5;
    __shared__ float sq0[128];
    __shared__ float sproj[1024];
    __shared__ __align__(16) float sq[128];
    __shared__ float su[Nn];
    __shared__ float rv[1024];
    __shared__ int ri[1024];

    if (tid < 128) sq0[tid] = d_qb[b * Hh + tid];
    __syncthreads();
    {
        int h = tid & 127, part = tid >> 7;   // 8 parts x 16 rows
        int i0 = part * 16;
        float acc = 0.f;
#pragma unroll
        for (int i = i0; i < i0 + 16; i++) acc = fmaf(sq0[i], Wq2[(size_t)i * Hh + h], acc);
        sproj[tid] = acc;
        __syncthreads();
        if (tid < 128) {
            float s = 0.f;
#pragma unroll
            for (int p = 0; p < 8; p++) s += sproj[tid + p * 128];
            sq[tid] = s;
        }
        __syncthreads();
    }

    float4 q4 = *(float4*)&sq[lane * 4];
    float4 v2 = *(const float4*)&Vec2[lane * 4];
    for (int n = w; n < Nn; n += 32) {
        float4 r4 = *(const float4*)&d_r2[(size_t)(b * Nn + n) * Hh + lane * 4];
        float dot = fast_tanh(q4.x + r4.x) * v2.x;
        dot = fmaf(fast_tanh(q4.y + r4.y), v2.y, dot);
        dot = fmaf(fast_tanh(q4.z + r4.z), v2.z, dot);
        dot = fmaf(fast_tanh(q4.w + r4.w), v2.w, dot);
#pragma unroll
        for (int off = 16; off; off >>= 1) dot += __shfl_xor_sync(0xffffffffu, dot, off);
        if (lane == 0) su[n] = CCLIP * fast_tanh(dot) - NEGC * d_mask[b * Nn + n];
    }
    __syncthreads();

    // argmax (first index wins on ties, matching jnp.argmax)
    float best = (tid < Nn) ? su[tid] : -1e30f;
    int bidx = (tid < Nn) ? tid : 0;
    rv[tid] = best; ri[tid] = bidx;
    __syncthreads();
    for (int sstep = 512; sstep; sstep >>= 1) {
        if (tid < sstep) {
            float v2r = rv[tid + sstep]; int i2 = ri[tid + sstep];
            if (v2r > rv[tid] || (v2r == rv[tid] && i2 < ri[tid])) { rv[tid] = v2r; ri[tid] = i2; }
        }
        __syncthreads();
    }
    float umax = rv[0]; int sel = ri[0];

    // fixed-shift log-sum-exp: u <= 10 always
    float z = (tid < Nn) ? __expf(su[tid] - CCLIP) : 0.f;
    sproj[tid] = z;
    __syncthreads();
    for (int sstep = 512; sstep; sstep >>= 1) {
        if (tid < sstep) sproj[tid] += sproj[tid + sstep];
        __syncthreads();
    }
    float lse = CCLIP + __logf(sproj[0]);
    (void)umax;

    if (tid < Nn)
        out[((size_t)t * Bb + b) * Nn + tid] = su[tid] - lse;

    if (tid == 0) {
        out[(size_t)Tt * Bb * Nn + t * Bb + b] = (float)sel;
        d_mask[b * Nn + sel] = 1.0f;
    }
    if (tid < 128)
        d_q0[b * 256 + 128 + tid] = enc[((size_t)b * Nn + sel) * Hh + tid];
}

// ---------------- host launcher ----------------
extern "C" void kernel_launch(void* const* d_in, const int* in_sizes, int n_in,
                              void* d_out, int out_size) {
    const float* enc    = (const float*)d_in[0];
    const float* mask0  = (const float*)d_in[1];
    const float* Wq1    = (const float*)d_in[2];
    const float* Wref1  = (const float*)d_in[3];
    const float* Vec1   = (const float*)d_in[4];
    const float* Wq3    = (const float*)d_in[5];
    const float* Wref3  = (const float*)d_in[6];
    const float* Vec3   = (const float*)d_in[7];
    const float* Wq4    = (const float*)d_in[8];
    const float* Wref4  = (const float*)d_in[9];
    const float* Vec4   = (const float*)d_in[10];
    const float* Wmh    = (const float*)d_in[11];
    const float* Wq2    = (const float*)d_in[12];
    const float* Wref2  = (const float*)d_in[13];
    const float* Vec2   = (const float*)d_in[14];
    const float* dec_inp = (const float*)d_in[15];
    float* out = (float*)d_out;

    GemmW gw{Wref1, Vec1, Wref3, Vec3, Wref4, Vec4, Wref2};
    gemm_kernel<<<dim3(125, 13), 256>>>(enc, gw);
    hmean_kernel<<<Bb, 256>>>(enc);
    init_kernel<<<Bb, 256>>>(mask0, dec_inp);

    for (int t = 0; t < Tt; t++) {
        glimpse_chunk<<<dim3(Ss, Mm, Bb), 256>>>(0, 256, Wq1);
        glimpse_combine<<<Bb, 256>>>(Wmh);
        glimpse_chunk<<<dim3(Ss, Mm, Bb), 256>>>(1, 128, Wq3);
        glimpse_combine<<<Bb, 256>>>(Wmh);
        glimpse_chunk<<<dim3(Ss, Mm, Bb), 256>>>(2, 128, Wq4);
        glimpse_combine<<<Bb, 256>>>(Wmh);
        pointer_kernel<<<Bb, 1024>>>(enc, Wq2, Vec2, out, t);
    }
    (void)in_sizes; (void)n_in; (void)out_size;
}

// round 6
// speedup vs baseline: 2.6857x; 1.1932x over previous
#include <cuda_runtime.h>
#include <math.h>

#define Bb 16
#define Nn 1000
#define Hh 128
#define Mm 2
#define Tt 16
#define Ss 25         // chunks per (b,m): CN rows each
#define CN 40         // Nn / Ss; 8 warps x 5 rows
#define NEGC 1e8f
#define CCLIP 10.0f

// ---------------- scratch (static device globals; no allocation) ----------------
#define BNH (Bb*Nn*Hh)
__device__ __align__(16) float d_r1[Mm*BNH];
__device__ __align__(16) float d_v1[Mm*BNH];
__device__ __align__(16) float d_r3[Mm*BNH];
__device__ __align__(16) float d_v3[Mm*BNH];
__device__ __align__(16) float d_r4[Mm*BNH];
__device__ __align__(16) float d_v4[Mm*BNH];
__device__ __align__(16) float d_r2[BNH];
__device__ __align__(16) float d_hmean[Bb*Hh];
__device__ __align__(16) float d_qproj[Bb*Mm*Hh];  // projected glimpse query per head
__device__ __align__(16) float d_qp2[Bb*Hh];       // projected pointer query
__device__ __align__(16) float d_mask[Bb*Nn];
__device__ __align__(16) float d_u[Bb*Nn];         // pointer logits
__device__ __align__(16) float d_pZ[Bb*Mm*Ss];
__device__ __align__(16) float d_pacc[Bb*Mm*Ss*Hh];

__device__ __forceinline__ float fast_tanh(float x) {
    float y;
    asm("tanh.approx.f32 %0, %1;" : "=f"(y) : "f"(x));
    return y;
}

// ---------------- precompute GEMM: 13 slabs of [16000x128] @ [128x128] ----------------
struct GemmW {
    const float* Wref1; const float* Vec1;
    const float* Wref3; const float* Vec3;
    const float* Wref4; const float* Vec4;
    const float* Wref2;
};

__global__ __launch_bounds__(256) void gemm_kernel(const float* __restrict__ A, GemmW gw) {
    __shared__ float As[8][132];
    __shared__ float Bs[8][132];

    int s = blockIdx.y;
    int m = s & 1;
    const float* W; float* D;
    switch (s >> 1) {
        case 0: W = gw.Wref1; D = d_r1; break;
        case 1: W = gw.Vec1;  D = d_v1; break;
        case 2: W = gw.Wref3; D = d_r3; break;
        case 3: W = gw.Vec3;  D = d_v3; break;
        case 4: W = gw.Wref4; D = d_r4; break;
        case 5: W = gw.Vec4;  D = d_v4; break;
        default: W = gw.Wref2; D = d_r2; break;   // s==12 -> m==0
    }
    W += (size_t)m * Hh * Hh;
    D += (size_t)m * BNH;

    int tid = threadIdx.x;
    int tx = tid & 15, ty = tid >> 4;
    int rowBase = blockIdx.x * 128;

    int arow = tid >> 1, akq = (tid & 1) * 4;
    int brow = tid >> 5, bcol = (tid & 31) * 4;

    float acc[8][8];
#pragma unroll
    for (int i = 0; i < 8; i++)
#pragma unroll
        for (int j = 0; j < 8; j++) acc[i][j] = 0.f;

    for (int k0 = 0; k0 < 128; k0 += 8) {
        float4 av = *(const float4*)&A[(size_t)(rowBase + arow) * 128 + k0 + akq];
        As[akq + 0][arow] = av.x;
        As[akq + 1][arow] = av.y;
        As[akq + 2][arow] = av.z;
        As[akq + 3][arow] = av.w;
        float4 bv = *(const float4*)&W[(size_t)(k0 + brow) * 128 + bcol];
        *(float4*)&Bs[brow][bcol] = bv;
        __syncthreads();
#pragma unroll
        for (int kk = 0; kk < 8; kk++) {
            float4 a0 = *(float4*)&As[kk][ty * 8];
            float4 a1 = *(float4*)&As[kk][ty * 8 + 4];
            float4 b0 = *(float4*)&Bs[kk][tx * 4];
            float4 b1 = *(float4*)&Bs[kk][64 + tx * 4];
            float a[8] = {a0.x, a0.y, a0.z, a0.w, a1.x, a1.y, a1.z, a1.w};
            float b[8] = {b0.x, b0.y, b0.z, b0.w, b1.x, b1.y, b1.z, b1.w};
#pragma unroll
            for (int i = 0; i < 8; i++)
#pragma unroll
                for (int j = 0; j < 8; j++) acc[i][j] = fmaf(a[i], b[j], acc[i][j]);
        }
        __syncthreads();
    }

    int r0 = rowBase + ty * 8;
#pragma unroll
    for (int i = 0; i < 8; i++) {
        float4 o0 = make_float4(acc[i][0], acc[i][1], acc[i][2], acc[i][3]);
        float4 o1 = make_float4(acc[i][4], acc[i][5], acc[i][6], acc[i][7]);
        *(float4*)&D[(size_t)(r0 + i) * Hh + tx * 4] = o0;
        *(float4*)&D[(size_t)(r0 + i) * Hh + 64 + tx * 4] = o1;
    }
}

// ---------------- h_mean ----------------
__global__ __launch_bounds__(256) void hmean_kernel(const float* __restrict__ enc) {
    int b = blockIdx.x;
    int h = threadIdx.x & 127;
    int part = threadIdx.x >> 7;
    float sum = 0.f;
    int n0 = part * 500;
    for (int n = n0; n < n0 + 500; n++) sum += enc[(size_t)(b * Nn + n) * Hh + h];
    __shared__ float sp[256];
    sp[threadIdx.x] = sum;
    __syncthreads();
    if (part == 0) d_hmean[b * Hh + h] = (sp[h] + sp[128 + h]) * (1.0f / (float)Nn);
}

// ---------------- init: mask copy + first-step Wq1 projection ----------------
__global__ __launch_bounds__(256) void init_kernel(const float* __restrict__ mask0,
                                                   const float* __restrict__ dec_inp,
                                                   const float* __restrict__ Wq1) {
    int b = blockIdx.x, tid = threadIdx.x;
    __shared__ float sq0[256];
    sq0[tid] = (tid < 128) ? d_hmean[b * Hh + tid] : dec_inp[tid - 128];
    for (int n = tid; n < Nn; n += 256) d_mask[b * Nn + n] = mask0[b * Nn + n];
    __syncthreads();
    int m = tid >> 7, h = tid & 127;
    const float* W = Wq1 + (size_t)m * 256 * Hh;
    float acc = 0.f;
#pragma unroll 8
    for (int i = 0; i < 256; i++) acc = fmaf(sq0[i], W[(size_t)i * Hh + h], acc);
    d_qproj[(b * Mm + m) * Hh + h] = acc;
}

// ---------------- glimpse chunk: MLP-batched fixed-shift softmax partials ----------
// grid (Ss, Mm, Bb), 256 threads = 8 warps x 5 rows each. Query pre-projected.
__global__ __launch_bounds__(256, 3) void glimpse_chunk(int which) {
    const float* rT = (which == 0) ? d_r1 : (which == 1) ? d_r3 : d_r4;
    const float* vT = (which == 0) ? d_v1 : (which == 1) ? d_v3 : d_v4;

    int c = blockIdx.x, m = blockIdx.y, b = blockIdx.z;
    int tid = threadIdx.x, lane = tid & 31, w = tid >> 5;

    __shared__ float wZ[8];
    __shared__ __align__(16) float wacc[8 * 128];

    float4 q4 = *(const float4*)&d_qproj[((size_t)(b * Mm + m)) * Hh + lane * 4];
    const float* rBase = rT + (size_t)(m * Bb + b) * Nn * Hh;
    const float* vBase = vT + (size_t)(m * Bb + b) * Nn * Hh;
    const float* maskb = d_mask + b * Nn;

    int n0 = c * CN + w;

    // front-batched loads: 11 independent LDGs in flight
    float4 r[5], v[5];
    float mk[5];
#pragma unroll
    for (int i = 0; i < 5; i++) {
        int n = n0 + i * 8;
        r[i] = *(const float4*)&rBase[(size_t)n * Hh + lane * 4];
        v[i] = *(const float4*)&vBase[(size_t)n * Hh + lane * 4];
        mk[i] = maskb[n];
    }

    float dot[5];
#pragma unroll
    for (int i = 0; i < 5; i++) {
        float d = fast_tanh(q4.x + r[i].x) * v[i].x;
        d = fmaf(fast_tanh(q4.y + r[i].y), v[i].y, d);
        d = fmaf(fast_tanh(q4.z + r[i].z), v[i].z, d);
        d = fmaf(fast_tanh(q4.w + r[i].w), v[i].w, d);
        dot[i] = d;
    }
    // 5 interleaved butterfly reductions (independent chains hide shfl latency)
#pragma unroll
    for (int off = 16; off; off >>= 1) {
#pragma unroll
        for (int i = 0; i < 5; i++) dot[i] += __shfl_xor_sync(0xffffffffu, dot[i], off);
    }

    float Z = 0.f;
    float4 racc = make_float4(0.f, 0.f, 0.f, 0.f);
#pragma unroll
    for (int i = 0; i < 5; i++) {
        // p = exp(10*tanh(dot) - 10 - 1e8*mask); <= 1, masked -> exactly 0
        float p = __expf(fmaf(CCLIP, fast_tanh(dot[i]), -CCLIP) - NEGC * mk[i]);
        Z += p;
        racc.x = fmaf(p, r[i].x, racc.x);
        racc.y = fmaf(p, r[i].y, racc.y);
        racc.z = fmaf(p, r[i].z, racc.z);
        racc.w = fmaf(p, r[i].w, racc.w);
    }

    if (lane == 0) wZ[w] = Z;
    *(float4*)&wacc[w * 128 + lane * 4] = racc;
    __syncthreads();

    if (tid < 128) {
        float z = 0.f, g = 0.f;
#pragma unroll
        for (int j = 0; j < 8; j++) {
            z += wZ[j];
            g += wacc[j * 128 + tid];
        }
        int pidx = (b * Mm + m) * Ss + c;
        d_pacc[pidx * Hh + tid] = g;
        if (tid == 0) d_pZ[pidx] = z;
    }
}

// ---------------- combine: merge chunks + heads, project NEXT query --------------
// last==0: project with Wqnext[M,H,H] -> d_qproj. last==1: project with Wq2[H,H] -> d_qp2.
__global__ __launch_bounds__(256) void glimpse_combine(const float* __restrict__ Wmh,
                                                       const float* __restrict__ Wqnext,
                                                       int last,
                                                       const float* __restrict__ Wq2) {
    int b = blockIdx.x, tid = threadIdx.x;   // tid = m*128 + h
    __shared__ float sg[256];
    __shared__ float sp2[256];
    __shared__ __align__(16) float sqb[128];
    int base = (b * Mm + (tid >> 7)) * Ss;
    int h = tid & 127;
    float z = 0.f, g = 0.f;
#pragma unroll
    for (int c = 0; c < Ss; c++) {
        z += d_pZ[base + c];
        g += d_pacc[(base + c) * Hh + h];
    }
    sg[tid] = g / z;
    __syncthreads();
    // qb[h] = sum_j sg[j] * Wmh[j,h]
    {
        int part = tid >> 7;
        int j0 = part * 128;
        float o = 0.f;
#pragma unroll 8
        for (int j = j0; j < j0 + 128; j++) o = fmaf(sg[j], Wmh[(size_t)j * Hh + h], o);
        sp2[tid] = o;
        __syncthreads();
        if (part == 0) sqb[h] = sp2[h] + sp2[128 + h];
        __syncthreads();
    }
    if (!last) {
        int m = tid >> 7;
        const float* W = Wqnext + (size_t)m * Hh * Hh;
        float acc = 0.f;
#pragma unroll 8
        for (int i = 0; i < 128; i++) acc = fmaf(sqb[i], W[(size_t)i * Hh + h], acc);
        d_qproj[(b * Mm + m) * Hh + h] = acc;
    } else {
        int part = tid >> 7;
        int i0 = part * 64;
        float acc = 0.f;
#pragma unroll 8
        for (int i = i0; i < i0 + 64; i++) acc = fmaf(sqb[i], Wq2[(size_t)i * Hh + h], acc);
        sp2[tid] = acc;
        __syncthreads();
        if (part == 0) d_qp2[b * Hh + h] = sp2[h] + sp2[128 + h];
    }
}

// ---------------- pointer logits: MLP-batched chunked scan over r2 ----------------
// grid (Ss, Bb), 256 threads = 8 warps x 5 rows.
__global__ __launch_bounds__(256, 3) void logits_chunk(const float* __restrict__ Vec2) {
    int c = blockIdx.x, b = blockIdx.y;
    int tid = threadIdx.x, lane = tid & 31, w = tid >> 5;

    float4 q4 = *(const float4*)&d_qp2[b * Hh + lane * 4];
    float4 v2 = *(const float4*)&Vec2[lane * 4];
    const float* rBase = d_r2 + (size_t)b * Nn * Hh;
    const float* maskb = d_mask + b * Nn;

    int n0 = c * CN + w;
    float4 r[5];
    float mk[5];
#pragma unroll
    for (int i = 0; i < 5; i++) {
        int n = n0 + i * 8;
        r[i] = *(const float4*)&rBase[(size_t)n * Hh + lane * 4];
        mk[i] = maskb[n];
    }
    float dot[5];
#pragma unroll
    for (int i = 0; i < 5; i++) {
        float d = fast_tanh(q4.x + r[i].x) * v2.x;
        d = fmaf(fast_tanh(q4.y + r[i].y), v2.y, d);
        d = fmaf(fast_tanh(q4.z + r[i].z), v2.z, d);
        d = fmaf(fast_tanh(q4.w + r[i].w), v2.w, d);
        dot[i] = d;
    }
#pragma unroll
    for (int off = 16; off; off >>= 1) {
#pragma unroll
        for (int i = 0; i < 5; i++) dot[i] += __shfl_xor_sync(0xffffffffu, dot[i], off);
    }
    if (lane == 0) {
#pragma unroll
        for (int i = 0; i < 5; i++)
            d_u[b * Nn + n0 + i * 8] = CCLIP * fast_tanh(dot[i]) - NEGC * mk[i];
    }
}

// ---------------- finalize: log_softmax, argmax, output, state, next projection ----
__global__ __launch_bounds__(1024) void pointer_finalize(const float* __restrict__ enc,
                                                         const float* __restrict__ Wq1,
                                                         float* __restrict__ out, int t) {
    int b = blockIdx.x, tid = threadIdx.x;
    __shared__ float rv[1024];
    __shared__ int ri[1024];
    __shared__ float sred[1024];
    __shared__ float sq0[256];

    float u = (tid < Nn) ? d_u[b * Nn + tid] : -1e30f;

    // argmax (first index wins on ties)
    rv[tid] = u; ri[tid] = (tid < Nn) ? tid : 0;
    __syncthreads();
#pragma unroll
    for (int s = 512; s; s >>= 1) {
        if (tid < s) {
            float v2 = rv[tid + s]; int i2 = ri[tid + s];
            if (v2 > rv[tid] || (v2 == rv[tid] && i2 < ri[tid])) { rv[tid] = v2; ri[tid] = i2; }
        }
        __syncthreads();
    }
    int sel = ri[0];

    // fixed-shift lse: u <= 10 always
    sred[tid] = (tid < Nn) ? __expf(u - CCLIP) : 0.f;
    __syncthreads();
#pragma unroll
    for (int s = 512; s; s >>= 1) {
        if (tid < s) sred[tid] += sred[tid + s];
        __syncthreads();
    }
    float lse = CCLIP + __logf(sred[0]);

    if (tid < Nn)
        out[((size_t)t * Bb + b) * Nn + tid] = u - lse;
    if (tid == 0) {
        out[(size_t)Tt * Bb * Nn + t * Bb + b] = (float)sel;
        d_mask[b * Nn + sel] = 1.0f;
    }

    // q0 = [h_mean, enc[b, sel]]; project with Wq1 for next step's glimpse 1
    if (tid < 256)
        sq0[tid] = (tid < 128) ? d_hmean[b * Hh + tid]
                               : enc[((size_t)b * Nn + sel) * Hh + (tid - 128)];
    __syncthreads();
    {
        int part = tid >> 8;          // 4 parts
        int mh = tid & 255;
        int m = mh >> 7, h = mh & 127;
        const float* W = Wq1 + (size_t)m * 256 * Hh;
        int i0 = part * 64;
        float acc = 0.f;
#pragma unroll 8
        for (int i = i0; i < i0 + 64; i++) acc = fmaf(sq0[i], W[(size_t)i * Hh + h], acc);
        sred[tid] = acc;
        __syncthreads();
        if (tid < 256) {
            float a = sred[tid] + sred[tid + 256] + sred[tid + 512] + sred[tid + 768];
            d_qproj[(b * Mm + m) * Hh + h] = a;
        }
    }
}

// ---------------- host launcher ----------------
extern "C" void kernel_launch(void* const* d_in, const int* in_sizes, int n_in,
                              void* d_out, int out_size) {
    const float* enc    = (const float*)d_in[0];
    const float* mask0  = (const float*)d_in[1];
    const float* Wq1    = (const float*)d_in[2];
    const float* Wref1  = (const float*)d_in[3];
    const float* Vec1   = (const float*)d_in[4];
    const float* Wq3    = (const float*)d_in[5];
    const float* Wref3  = (const float*)d_in[6];
    const float* Vec3   = (const float*)d_in[7];
    const float* Wq4    = (const float*)d_in[8];
    const float* Wref4  = (const float*)d_in[9];
    const float* Vec4   = (const float*)d_in[10];
    const float* Wmh    = (const float*)d_in[11];
    const float* Wq2    = (const float*)d_in[12];
    const float* Wref2  = (const float*)d_in[13];
    const float* Vec2   = (const float*)d_in[14];
    const float* dec_inp = (const float*)d_in[15];
    float* out = (float*)d_out;

    GemmW gw{Wref1, Vec1, Wref3, Vec3, Wref4, Vec4, Wref2};
    gemm_kernel<<<dim3(125, 13), 256>>>(enc, gw);
    hmean_kernel<<<Bb, 256>>>(enc);
    init_kernel<<<Bb, 256>>>(mask0, dec_inp, Wq1);

    for (int t = 0; t < Tt; t++) {
        glimpse_chunk<<<dim3(Ss, Mm, Bb), 256>>>(0);
        glimpse_combine<<<Bb, 256>>>(Wmh, Wq3, 0, Wq2);
        glimpse_chunk<<<dim3(Ss, Mm, Bb), 256>>>(1);
        glimpse_combine<<<Bb, 256>>>(Wmh, Wq4, 0, Wq2);
        glimpse_chunk<<<dim3(Ss, Mm, Bb), 256>>>(2);
        glimpse_combine<<<Bb, 256>>>(Wmh, Wq4, 1, Wq2);
        logits_chunk<<<dim3(Ss, Bb), 256>>>(Vec2);
        pointer_finalize<<<Bb, 1024>>>(enc, Wq1, out, t);
    }
    (void)in_sizes; (void)n_in; (void)out_size;
}

// round 7
// speedup vs baseline: 3.6530x; 1.3602x over previous
#include <cuda_runtime.h>
#include <cuda_bf16.h>
#include <math.h>

#define Bb 16
#define Nn 1000
#define Hh 128
#define Mm 2
#define Tt 16
#define Ss 25         // chunks per (b,m): CN rows each
#define CN 40         // Nn / Ss; 8 warps x 5 rows
#define NEGC 1e8f
#define CCLIP 10.0f

// ---------------- scratch (static device globals; no allocation) ----------------
#define BNH (Bb*Nn*Hh)
__device__ __align__(16) __nv_bfloat16 d_r1[Mm*BNH];
__device__ __align__(16) __nv_bfloat16 d_v1[Mm*BNH];
__device__ __align__(16) __nv_bfloat16 d_r3[Mm*BNH];
__device__ __align__(16) __nv_bfloat16 d_v3[Mm*BNH];
__device__ __align__(16) __nv_bfloat16 d_r4[Mm*BNH];
__device__ __align__(16) __nv_bfloat16 d_v4[Mm*BNH];
__device__ __align__(16) float d_r2[BNH];          // pointer path stays fp32
__device__ __align__(16) float d_hmean[Bb*Hh];
__device__ __align__(16) float d_qproj[Bb*Mm*Hh];  // projected glimpse query per head
__device__ __align__(16) float d_qp2[Bb*Hh];       // projected pointer query
__device__ __align__(16) float d_mask[Bb*Nn];
__device__ __align__(16) float d_u[Bb*Nn];         // pointer logits
__device__ __align__(16) float d_pZ[Bb*Mm*Ss];
__device__ __align__(16) float d_pacc[Bb*Mm*Ss*Hh];

__device__ __forceinline__ float fast_tanh(float x) {
    float y;
    asm("tanh.approx.f32 %0, %1;" : "=f"(y) : "f"(x));
    return y;
}

// ---------------- precompute GEMM: 13 slabs of [16000x128] @ [128x128] ----------------
// Slabs 0..11 (r/v glimpse tensors) store bf16; slab 12 (r2) stores fp32.
struct GemmW {
    const float* Wref1; const float* Vec1;
    const float* Wref3; const float* Vec3;
    const float* Wref4; const float* Vec4;
    const float* Wref2;
};

__global__ __launch_bounds__(256) void gemm_kernel(const float* __restrict__ A, GemmW gw) {
    __shared__ float As[8][132];
    __shared__ float Bs[8][132];

    int s = blockIdx.y;
    int m = s & 1;
    const float* W;
    __nv_bfloat16* Db = nullptr;
    float* Df = nullptr;
    switch (s >> 1) {
        case 0: W = gw.Wref1; Db = d_r1; break;
        case 1: W = gw.Vec1;  Db = d_v1; break;
        case 2: W = gw.Wref3; Db = d_r3; break;
        case 3: W = gw.Vec3;  Db = d_v3; break;
        case 4: W = gw.Wref4; Db = d_r4; break;
        case 5: W = gw.Vec4;  Db = d_v4; break;
        default: W = gw.Wref2; Df = d_r2; break;   // s==12 -> m==0
    }
    W += (size_t)m * Hh * Hh;
    if (Db) Db += (size_t)m * BNH;

    int tid = threadIdx.x;
    int tx = tid & 15, ty = tid >> 4;
    int rowBase = blockIdx.x * 128;

    int arow = tid >> 1, akq = (tid & 1) * 4;
    int brow = tid >> 5, bcol = (tid & 31) * 4;

    float acc[8][8];
#pragma unroll
    for (int i = 0; i < 8; i++)
#pragma unroll
        for (int j = 0; j < 8; j++) acc[i][j] = 0.f;

    for (int k0 = 0; k0 < 128; k0 += 8) {
        float4 av = *(const float4*)&A[(size_t)(rowBase + arow) * 128 + k0 + akq];
        As[akq + 0][arow] = av.x;
        As[akq + 1][arow] = av.y;
        As[akq + 2][arow] = av.z;
        As[akq + 3][arow] = av.w;
        float4 bv = *(const float4*)&W[(size_t)(k0 + brow) * 128 + bcol];
        *(float4*)&Bs[brow][bcol] = bv;
        __syncthreads();
#pragma unroll
        for (int kk = 0; kk < 8; kk++) {
            float4 a0 = *(float4*)&As[kk][ty * 8];
            float4 a1 = *(float4*)&As[kk][ty * 8 + 4];
            float4 b0 = *(float4*)&Bs[kk][tx * 4];
            float4 b1 = *(float4*)&Bs[kk][64 + tx * 4];
            float a[8] = {a0.x, a0.y, a0.z, a0.w, a1.x, a1.y, a1.z, a1.w};
            float b[8] = {b0.x, b0.y, b0.z, b0.w, b1.x, b1.y, b1.z, b1.w};
#pragma unroll
            for (int i = 0; i < 8; i++)
#pragma unroll
                for (int j = 0; j < 8; j++) acc[i][j] = fmaf(a[i], b[j], acc[i][j]);
        }
        __syncthreads();
    }

    int r0 = rowBase + ty * 8;
    if (Db) {
#pragma unroll
        for (int i = 0; i < 8; i++) {
            __nv_bfloat162 p01 = __floats2bfloat162_rn(acc[i][0], acc[i][1]);
            __nv_bfloat162 p23 = __floats2bfloat162_rn(acc[i][2], acc[i][3]);
            __nv_bfloat162 p45 = __floats2bfloat162_rn(acc[i][4], acc[i][5]);
            __nv_bfloat162 p67 = __floats2bfloat162_rn(acc[i][6], acc[i][7]);
            uint2 lo, hi;
            lo.x = *(unsigned int*)&p01; lo.y = *(unsigned int*)&p23;
            hi.x = *(unsigned int*)&p45; hi.y = *(unsigned int*)&p67;
            *(uint2*)&Db[(size_t)(r0 + i) * Hh + tx * 4] = lo;
            *(uint2*)&Db[(size_t)(r0 + i) * Hh + 64 + tx * 4] = hi;
        }
    } else {
#pragma unroll
        for (int i = 0; i < 8; i++) {
            float4 o0 = make_float4(acc[i][0], acc[i][1], acc[i][2], acc[i][3]);
            float4 o1 = make_float4(acc[i][4], acc[i][5], acc[i][6], acc[i][7]);
            *(float4*)&Df[(size_t)(r0 + i) * Hh + tx * 4] = o0;
            *(float4*)&Df[(size_t)(r0 + i) * Hh + 64 + tx * 4] = o1;
        }
    }
}

// ---------------- h_mean ----------------
__global__ __launch_bounds__(256) void hmean_kernel(const float* __restrict__ enc) {
    int b = blockIdx.x;
    int h = threadIdx.x & 127;
    int part = threadIdx.x >> 7;
    float sum = 0.f;
    int n0 = part * 500;
    for (int n = n0; n < n0 + 500; n++) sum += enc[(size_t)(b * Nn + n) * Hh + h];
    __shared__ float sp[256];
    sp[threadIdx.x] = sum;
    __syncthreads();
    if (part == 0) d_hmean[b * Hh + h] = (sp[h] + sp[128 + h]) * (1.0f / (float)Nn);
}

// ---------------- init: mask copy + first-step Wq1 projection ----------------
__global__ __launch_bounds__(256) void init_kernel(const float* __restrict__ mask0,
                                                   const float* __restrict__ dec_inp,
                                                   const float* __restrict__ Wq1) {
    int b = blockIdx.x, tid = threadIdx.x;
    __shared__ float sq0[256];
    sq0[tid] = (tid < 128) ? d_hmean[b * Hh + tid] : dec_inp[tid - 128];
    for (int n = tid; n < Nn; n += 256) d_mask[b * Nn + n] = mask0[b * Nn + n];
    __syncthreads();
    int m = tid >> 7, h = tid & 127;
    const float* W = Wq1 + (size_t)m * 256 * Hh;
    float acc = 0.f;
#pragma unroll 8
    for (int i = 0; i < 256; i++) acc = fmaf(sq0[i], W[(size_t)i * Hh + h], acc);
    d_qproj[(b * Mm + m) * Hh + h] = acc;
}

// ---------------- glimpse chunk: bf16 streams, MLP-batched fixed-shift softmax ------
// grid (Ss, Mm, Bb), 256 threads = 8 warps x 5 rows each. Query pre-projected.
__global__ __launch_bounds__(256, 4) void glimpse_chunk(int which) {
    const __nv_bfloat16* rT = (which == 0) ? d_r1 : (which == 1) ? d_r3 : d_r4;
    const __nv_bfloat16* vT = (which == 0) ? d_v1 : (which == 1) ? d_v3 : d_v4;

    int c = blockIdx.x, m = blockIdx.y, b = blockIdx.z;
    int tid = threadIdx.x, lane = tid & 31, w = tid >> 5;

    __shared__ float wZ[8];
    __shared__ __align__(16) float wacc[8 * 128];

    float4 q4 = *(const float4*)&d_qproj[((size_t)(b * Mm + m)) * Hh + lane * 4];
    const __nv_bfloat16* rBase = rT + (size_t)(m * Bb + b) * Nn * Hh;
    const __nv_bfloat16* vBase = vT + (size_t)(m * Bb + b) * Nn * Hh;
    const float* maskb = d_mask + b * Nn;

    int n0 = c * CN + w;

    // front-batched loads: 11 independent LDGs in flight (8B each for r/v)
    uint2 rw[5], vw[5];
    float mk[5];
#pragma unroll
    for (int i = 0; i < 5; i++) {
        int n = n0 + i * 8;
        rw[i] = *(const uint2*)&rBase[(size_t)n * Hh + lane * 4];
        vw[i] = *(const uint2*)&vBase[(size_t)n * Hh + lane * 4];
        mk[i] = maskb[n];
    }

    float rf[5][4], vf[5][4];
#pragma unroll
    for (int i = 0; i < 5; i++) {
        float2 r01 = __bfloat1622float2(*(__nv_bfloat162*)&rw[i].x);
        float2 r23 = __bfloat1622float2(*(__nv_bfloat162*)&rw[i].y);
        float2 v01 = __bfloat1622float2(*(__nv_bfloat162*)&vw[i].x);
        float2 v23 = __bfloat1622float2(*(__nv_bfloat162*)&vw[i].y);
        rf[i][0] = r01.x; rf[i][1] = r01.y; rf[i][2] = r23.x; rf[i][3] = r23.y;
        vf[i][0] = v01.x; vf[i][1] = v01.y; vf[i][2] = v23.x; vf[i][3] = v23.y;
    }

    float dot[5];
#pragma unroll
    for (int i = 0; i < 5; i++) {
        float d = fast_tanh(q4.x + rf[i][0]) * vf[i][0];
        d = fmaf(fast_tanh(q4.y + rf[i][1]), vf[i][1], d);
        d = fmaf(fast_tanh(q4.z + rf[i][2]), vf[i][2], d);
        d = fmaf(fast_tanh(q4.w + rf[i][3]), vf[i][3], d);
        dot[i] = d;
    }
    // 5 interleaved butterfly reductions (independent chains hide shfl latency)
#pragma unroll
    for (int off = 16; off; off >>= 1) {
#pragma unroll
        for (int i = 0; i < 5; i++) dot[i] += __shfl_xor_sync(0xffffffffu, dot[i], off);
    }

    float Z = 0.f;
    float4 racc = make_float4(0.f, 0.f, 0.f, 0.f);
#pragma unroll
    for (int i = 0; i < 5; i++) {
        // p = exp(10*tanh(dot) - 10 - 1e8*mask); <= 1, masked -> exactly 0
        float p = __expf(fmaf(CCLIP, fast_tanh(dot[i]), -CCLIP) - NEGC * mk[i]);
        Z += p;
        racc.x = fmaf(p, rf[i][0], racc.x);
        racc.y = fmaf(p, rf[i][1], racc.y);
        racc.z = fmaf(p, rf[i][2], racc.z);
        racc.w = fmaf(p, rf[i][3], racc.w);
    }

    if (lane == 0) wZ[w] = Z;
    *(float4*)&wacc[w * 128 + lane * 4] = racc;
    __syncthreads();

    if (tid < 128) {
        float z = 0.f, g = 0.f;
#pragma unroll
        for (int j = 0; j < 8; j++) {
            z += wZ[j];
            g += wacc[j * 128 + tid];
        }
        int pidx = (b * Mm + m) * Ss + c;
        d_pacc[pidx * Hh + tid] = g;
        if (tid == 0) d_pZ[pidx] = z;
    }
}

// ---------------- combine: merge chunks + heads, project NEXT query --------------
// last==0: project with Wqnext[M,H,H] -> d_qproj. last==1: project with Wq2[H,H] -> d_qp2.
__global__ __launch_bounds__(256) void glimpse_combine(const float* __restrict__ Wmh,
                                                       const float* __restrict__ Wqnext,
                                                       int last,
                                                       const float* __restrict__ Wq2) {
    int b = blockIdx.x, tid = threadIdx.x;   // tid = m*128 + h
    __shared__ float sg[256];
    __shared__ float sp2[256];
    __shared__ __align__(16) float sqb[128];
    int base = (b * Mm + (tid >> 7)) * Ss;
    int h = tid & 127;
    float z = 0.f, g = 0.f;
#pragma unroll
    for (int c = 0; c < Ss; c++) {
        z += d_pZ[base + c];
        g += d_pacc[(base + c) * Hh + h];
    }
    sg[tid] = g / z;
    __syncthreads();
    // qb[h] = sum_j sg[j] * Wmh[j,h]
    {
        int part = tid >> 7;
        int j0 = part * 128;
        float o = 0.f;
#pragma unroll 8
        for (int j = j0; j < j0 + 128; j++) o = fmaf(sg[j], Wmh[(size_t)j * Hh + h], o);
        sp2[tid] = o;
        __syncthreads();
        if (part == 0) sqb[h] = sp2[h] + sp2[128 + h];
        __syncthreads();
    }
    if (!last) {
        int m = tid >> 7;
        const float* W = Wqnext + (size_t)m * Hh * Hh;
        float acc = 0.f;
#pragma unroll 8
        for (int i = 0; i < 128; i++) acc = fmaf(sqb[i], W[(size_t)i * Hh + h], acc);
        d_qproj[(b * Mm + m) * Hh + h] = acc;
    } else {
        int part = tid >> 7;
        int i0 = part * 64;
        float acc = 0.f;
#pragma unroll 8
        for (int i = i0; i < i0 + 64; i++) acc = fmaf(sqb[i], Wq2[(size_t)i * Hh + h], acc);
        sp2[tid] = acc;
        __syncthreads();
        if (part == 0) d_qp2[b * Hh + h] = sp2[h] + sp2[128 + h];
    }
}

// ---------------- pointer logits: MLP-batched chunked scan over r2 (fp32) ----------
// grid (Ss, Bb), 256 threads = 8 warps x 5 rows.
__global__ __launch_bounds__(256, 3) void logits_chunk(const float* __restrict__ Vec2) {
    int c = blockIdx.x, b = blockIdx.y;
    int tid = threadIdx.x, lane = tid & 31, w = tid >> 5;

    float4 q4 = *(const float4*)&d_qp2[b * Hh + lane * 4];
    float4 v2 = *(const float4*)&Vec2[lane * 4];
    const float* rBase = d_r2 + (size_t)b * Nn * Hh;
    const float* maskb = d_mask + b * Nn;

    int n0 = c * CN + w;
    float4 r[5];
    float mk[5];
#pragma unroll
    for (int i = 0; i < 5; i++) {
        int n = n0 + i * 8;
        r[i] = *(const float4*)&rBase[(size_t)n * Hh + lane * 4];
        mk[i] = maskb[n];
    }
    float dot[5];
#pragma unroll
    for (int i = 0; i < 5; i++) {
        float d = fast_tanh(q4.x + r[i].x) * v2.x;
        d = fmaf(fast_tanh(q4.y + r[i].y), v2.y, d);
        d = fmaf(fast_tanh(q4.z + r[i].z), v2.z, d);
        d = fmaf(fast_tanh(q4.w + r[i].w), v2.w, d);
        dot[i] = d;
    }
#pragma unroll
    for (int off = 16; off; off >>= 1) {
#pragma unroll
        for (int i = 0; i < 5; i++) dot[i] += __shfl_xor_sync(0xffffffffu, dot[i], off);
    }
    if (lane == 0) {
#pragma unroll
        for (int i = 0; i < 5; i++)
            d_u[b * Nn + n0 + i * 8] = CCLIP * fast_tanh(dot[i]) - NEGC * mk[i];
    }
}

// ---------------- finalize: log_softmax, argmax, output, state, next projection ----
__global__ __launch_bounds__(1024) void pointer_finalize(const float* __restrict__ enc,
                                                         const float* __restrict__ Wq1,
                                                         float* __restrict__ out, int t) {
    int b = blockIdx.x, tid = threadIdx.x;
    __shared__ float rv[1024];
    __shared__ int ri[1024];
    __shared__ float sred[1024];
    __shared__ float sq0[256];

    float u = (tid < Nn) ? d_u[b * Nn + tid] : -1e30f;

    // argmax (first index wins on ties)
    rv[tid] = u; ri[tid] = (tid < Nn) ? tid : 0;
    __syncthreads();
#pragma unroll
    for (int s = 512; s; s >>= 1) {
        if (tid < s) {
            float v2 = rv[tid + s]; int i2 = ri[tid + s];
            if (v2 > rv[tid] || (v2 == rv[tid] && i2 < ri[tid])) { rv[tid] = v2; ri[tid] = i2; }
        }
        __syncthreads();
    }
    int sel = ri[0];

    // fixed-shift lse: u <= 10 always
    sred[tid] = (tid < Nn) ? __expf(u - CCLIP) : 0.f;
    __syncthreads();
#pragma unroll
    for (int s = 512; s; s >>= 1) {
        if (tid < s) sred[tid] += sred[tid + s];
        __syncthreads();
    }
    float lse = CCLIP + __logf(sred[0]);

    if (tid < Nn)
        out[((size_t)t * Bb + b) * Nn + tid] = u - lse;
    if (tid == 0) {
        out[(size_t)Tt * Bb * Nn + t * Bb + b] = (float)sel;
        d_mask[b * Nn + sel] = 1.0f;
    }

    // q0 = [h_mean, enc[b, sel]]; project with Wq1 for next step's glimpse 1
    if (tid < 256)
        sq0[tid] = (tid < 128) ? d_hmean[b * Hh + tid]
                               : enc[((size_t)b * Nn + sel) * Hh + (tid - 128)];
    __syncthreads();
    {
        int part = tid >> 8;          // 4 parts
        int mh = tid & 255;
        int m = mh >> 7, h = mh & 127;
        const float* W = Wq1 + (size_t)m * 256 * Hh;
        int i0 = part * 64;
        float acc = 0.f;
#pragma unroll 8
        for (int i = i0; i < i0 + 64; i++) acc = fmaf(sq0[i], W[(size_t)i * Hh + h], acc);
        sred[tid] = acc;
        __syncthreads();
        if (tid < 256) {
            float a = sred[tid] + sred[tid + 256] + sred[tid + 512] + sred[tid + 768];
            d_qproj[(b * Mm + m) * Hh + h] = a;
        }
    }
}

// ---------------- host launcher ----------------
extern "C" void kernel_launch(void* const* d_in, const int* in_sizes, int n_in,
                              void* d_out, int out_size) {
    const float* enc    = (const float*)d_in[0];
    const float* mask0  = (const float*)d_in[1];
    const float* Wq1    = (const float*)d_in[2];
    const float* Wref1  = (const float*)d_in[3];
    const float* Vec1   = (const float*)d_in[4];
    const float* Wq3    = (const float*)d_in[5];
    const float* Wref3  = (const float*)d_in[6];
    const float* Vec3   = (const float*)d_in[7];
    const float* Wq4    = (const float*)d_in[8];
    const float* Wref4  = (const float*)d_in[9];
    const float* Vec4   = (const float*)d_in[10];
    const float* Wmh    = (const float*)d_in[11];
    const float* Wq2    = (const float*)d_in[12];
    const float* Wref2  = (const float*)d_in[13];
    const float* Vec2   = (const float*)d_in[14];
    const float* dec_inp = (const float*)d_in[15];
    float* out = (float*)d_out;

    GemmW gw{Wref1, Vec1, Wref3, Vec3, Wref4, Vec4, Wref2};
    gemm_kernel<<<dim3(125, 13), 256>>>(enc, gw);
    hmean_kernel<<<Bb, 256>>>(enc);
    init_kernel<<<Bb, 256>>>(mask0, dec_inp, Wq1);

    for (int t = 0; t < Tt; t++) {
        glimpse_chunk<<<dim3(Ss, Mm, Bb), 256>>>(0);
        glimpse_combine<<<Bb, 256>>>(Wmh, Wq3, 0, Wq2);
        glimpse_chunk<<<dim3(Ss, Mm, Bb), 256>>>(1);
        glimpse_combine<<<Bb, 256>>>(Wmh, Wq4, 0, Wq2);
        glimpse_chunk<<<dim3(Ss, Mm, Bb), 256>>>(2);
        glimpse_combine<<<Bb, 256>>>(Wmh, Wq4, 1, Wq2);
        logits_chunk<<<dim3(Ss, Bb), 256>>>(Vec2);
        pointer_finalize<<<Bb, 1024>>>(enc, Wq1, out, t);
    }
    (void)in_sizes; (void)n_in; (void)out_size;
}